// round 2
// baseline (speedup 1.0000x reference)
#include <cuda_runtime.h>
#include <math.h>

// ---------------------------------------------------------------------------
// MLA prefill, fp32 baseline pipeline (register-prefetch pipelined GEMMs).
//   S=2048 tokens, HID=2048, H=16 heads, DN=128, DR=64, DV=128
//   QL=1536, KVL=512
// Stages:
//   0) pad w_fused_a [2048,2112] -> [2048,2176] so GEMM1 N % 128 == 0
//   1) a = hs @ w_fused_a_pad                (gemm128)
//   2) rmsnorm(q_lat), rmsnorm(ckv), rope(k_pe) in-place on a (stride 2176)
//   3) q  = q_lat @ w_q_b                    (gemm128)
//   4) kv = ckv  @ w_kv_b                    (gemm128)
//   5) rope(q_pe) in-place
//   6) scores[h,s,t] = q·k  (causal block skip, raw, unscaled)
//   7) row softmax (applies 1/sqrt(192) scale, zeros t>s)
//   8) att = p @ v  (k-limit per row block)
//   9) out = att @ w_o                       (gemm128)
// ---------------------------------------------------------------------------

#define S_    2048
#define HID_  2048
#define HEADS 16
#define DN_   128
#define DR_   64
#define DV_   128
#define QL_   1536
#define KVL_  512
#define AW_   2112            // QL+KVL+DR (true width)
#define APAD_ 2176            // padded width (17 * 128)
#define QW_   3072            // HEADS*(DN+DR)
#define KVW_  4096            // HEADS*(DN+DV)

// ------------------------------ scratch ------------------------------------
__device__ float g_wfa[(size_t)HID_ * APAD_];          // padded w_fused_a
__device__ float g_a  [(size_t)S_ * APAD_];            // fused-a output
__device__ float g_q  [(size_t)S_ * QW_];              // q (nope|pe per head)
__device__ float g_kv [(size_t)S_ * KVW_];             // kv (k_nope|v per head)
__device__ float g_att[(size_t)S_ * HEADS * DV_];      // attention output
__device__ float g_sc [(size_t)HEADS * S_ * S_];       // scores / probs

// --------------------------- generic GEMM 128x128x16 -----------------------
// C[M,N] = A[M,K] @ B[K,N], fp32, row-major with leading dims.
// grid = (N/128, M/128), 256 threads, 8x8 microtile, reg-prefetch pipeline.
__global__ __launch_bounds__(256) void gemm128(
    const float* __restrict__ A, const float* __restrict__ B,
    float* __restrict__ C, int K, int lda, int ldb, int ldc)
{
    __shared__ float As[16][128];
    __shared__ float Bs[16][128];
    const int tid = threadIdx.x;
    const int m0 = blockIdx.y * 128;
    const int n0 = blockIdx.x * 128;
    const int ty = tid >> 4, tx = tid & 15;

    const int ar0 = tid >> 2;            // 0..63 (A tile row, +64 second half)
    const int ac  = (tid & 3) << 2;      // 0,4,8,12 (A tile col base)
    const int bk0 = tid >> 5;            // 0..7 (B tile row, +8 second half)
    const int bc  = (tid & 31) << 2;     // 0..124 (B tile col base)

    const float* Ap = A + (size_t)(m0 + ar0) * lda + ac;
    const float* Bp = B + (size_t)bk0 * ldb + n0 + bc;

    float acc[8][8];
    #pragma unroll
    for (int i = 0; i < 8; i++)
        #pragma unroll
        for (int j = 0; j < 8; j++) acc[i][j] = 0.0f;

    const int nk = K >> 4;

    float4 pa0 = *(const float4*)(Ap);
    float4 pa1 = *(const float4*)(Ap + (size_t)64 * lda);
    float4 pb0 = *(const float4*)(Bp);
    float4 pb1 = *(const float4*)(Bp + (size_t)8 * ldb);

    for (int kt = 0; kt < nk; ++kt) {
        As[ac + 0][ar0]      = pa0.x;  As[ac + 1][ar0]      = pa0.y;
        As[ac + 2][ar0]      = pa0.z;  As[ac + 3][ar0]      = pa0.w;
        As[ac + 0][ar0 + 64] = pa1.x;  As[ac + 1][ar0 + 64] = pa1.y;
        As[ac + 2][ar0 + 64] = pa1.z;  As[ac + 3][ar0 + 64] = pa1.w;
        *(float4*)&Bs[bk0][bc]     = pb0;
        *(float4*)&Bs[bk0 + 8][bc] = pb1;
        __syncthreads();

        if (kt + 1 < nk) {                 // prefetch next tile into regs
            Ap += 16;
            Bp += (size_t)16 * ldb;
            pa0 = *(const float4*)(Ap);
            pa1 = *(const float4*)(Ap + (size_t)64 * lda);
            pb0 = *(const float4*)(Bp);
            pb1 = *(const float4*)(Bp + (size_t)8 * ldb);
        }

        #pragma unroll
        for (int k = 0; k < 16; ++k) {
            float4 av0 = *(const float4*)&As[k][ty * 8];
            float4 av1 = *(const float4*)&As[k][ty * 8 + 4];
            float4 bv0 = *(const float4*)&Bs[k][tx * 8];
            float4 bv1 = *(const float4*)&Bs[k][tx * 8 + 4];
            float aa[8] = {av0.x, av0.y, av0.z, av0.w, av1.x, av1.y, av1.z, av1.w};
            float bb[8] = {bv0.x, bv0.y, bv0.z, bv0.w, bv1.x, bv1.y, bv1.z, bv1.w};
            #pragma unroll
            for (int i = 0; i < 8; i++)
                #pragma unroll
                for (int j = 0; j < 8; j++) acc[i][j] += aa[i] * bb[j];
        }
        __syncthreads();
    }

    #pragma unroll
    for (int i = 0; i < 8; i++) {
        float* Cp = C + (size_t)(m0 + ty * 8 + i) * ldc + n0 + tx * 8;
        *(float4*)Cp       = make_float4(acc[i][0], acc[i][1], acc[i][2], acc[i][3]);
        *(float4*)(Cp + 4) = make_float4(acc[i][4], acc[i][5], acc[i][6], acc[i][7]);
    }
}

// ------------------------------ pad w_fused_a -------------------------------
__global__ void pad_wfa(const float* __restrict__ w)
{
    int idx = blockIdx.x * 256 + threadIdx.x;
    if (idx >= HID_ * APAD_) return;
    int r = idx / APAD_, c = idx - r * APAD_;
    g_wfa[idx] = (c < AW_) ? w[(size_t)r * AW_ + c] : 0.0f;
}

// --------------------- rmsnorm(q_lat, ckv) + rope(k_pe) ---------------------
__global__ __launch_bounds__(256) void norm_rope(
    const float* __restrict__ gq, const float* __restrict__ gkv,
    const int* __restrict__ pos)
{
    const int s = blockIdx.x;
    float* row = g_a + (size_t)s * APAD_;
    __shared__ float red[256];
    const int tid = threadIdx.x;

    // q latent rmsnorm (cols 0..1536)
    float ss = 0.0f;
    for (int i = tid; i < QL_; i += 256) { float v = row[i]; ss += v * v; }
    red[tid] = ss; __syncthreads();
    for (int o = 128; o > 0; o >>= 1) { if (tid < o) red[tid] += red[tid + o]; __syncthreads(); }
    __shared__ float rq_s;
    if (tid == 0) rq_s = rsqrtf(red[0] * (1.0f / QL_) + 1e-6f);
    __syncthreads();
    float rq = rq_s;
    for (int i = tid; i < QL_; i += 256) row[i] = row[i] * rq * gq[i];
    __syncthreads();

    // ckv rmsnorm (cols 1536..2048)
    ss = 0.0f;
    for (int i = tid; i < KVL_; i += 256) { float v = row[QL_ + i]; ss += v * v; }
    red[tid] = ss; __syncthreads();
    for (int o = 128; o > 0; o >>= 1) { if (tid < o) red[tid] += red[tid + o]; __syncthreads(); }
    __shared__ float rk_s;
    if (tid == 0) rk_s = rsqrtf(red[0] * (1.0f / KVL_) + 1e-6f);
    __syncthreads();
    float rk = rk_s;
    for (int i = tid; i < KVL_; i += 256) row[QL_ + i] = row[QL_ + i] * rk * gkv[i];

    // k_pe rope (cols 2048..2112), pairs (i, i+32)
    if (tid < 32) {
        int i = tid;
        float inv = 1.0f / powf(10000.0f, (float)(2 * i) * (1.0f / 64.0f));
        float ang = (float)pos[s] * inv;
        float c, sn; sincosf(ang, &sn, &c);
        float x1 = row[QL_ + KVL_ + i];
        float x2 = row[QL_ + KVL_ + 32 + i];
        row[QL_ + KVL_ + i]      = x1 * c - x2 * sn;
        row[QL_ + KVL_ + 32 + i] = x2 * c + x1 * sn;
    }
}

// ------------------------------- rope(q_pe) ---------------------------------
__global__ void rope_q(const int* __restrict__ pos)
{
    int idx = blockIdx.x * 256 + threadIdx.x;       // S*H*32 pairs
    if (idx >= S_ * HEADS * 32) return;
    int i = idx & 31;
    int h = (idx >> 5) & (HEADS - 1);
    int s = idx >> 9;
    size_t base = (size_t)s * QW_ + h * (DN_ + DR_) + DN_;
    float inv = 1.0f / powf(10000.0f, (float)(2 * i) * (1.0f / 64.0f));
    float ang = (float)pos[s] * inv;
    float c, sn; sincosf(ang, &sn, &c);
    float x1 = g_q[base + i], x2 = g_q[base + 32 + i];
    g_q[base + i]      = x1 * c - x2 * sn;
    g_q[base + 32 + i] = x2 * c + x1 * sn;
}

// ------------------------- scores: q . k  (causal skip) ---------------------
// grid (T/128, S/128, H). K = 192 (128 nope from kv, 64 pe from a).
__global__ __launch_bounds__(256) void attn_scores()
{
    const int h = blockIdx.z;
    const int sb = blockIdx.y;
    const int tb = blockIdx.x;
    if (tb > sb) return;   // fully masked

    __shared__ float As[16][128];
    __shared__ float Bs[16][128];
    const int tid = threadIdx.x;
    const int ty = tid >> 4, tx = tid & 15;
    const int ar0 = tid >> 2;
    const int ac  = (tid & 3) << 2;

    float acc[8][8];
    #pragma unroll
    for (int i = 0; i < 8; i++)
        #pragma unroll
        for (int j = 0; j < 8; j++) acc[i][j] = 0.0f;

    const float* Abase = g_q + (size_t)(sb * 128 + ar0) * QW_ + h * (DN_ + DR_);
    const int t = tb * 128 + ar0;
    const float* Bn = g_kv + (size_t)t * KVW_ + h * (DN_ + DV_);          // nope part
    const float* Bр = g_a + (size_t)t * APAD_ + (QL_ + KVL_);             // pe part

    // prefetch tile 0
    float4 pa0 = *(const float4*)(Abase + ac);
    float4 pa1 = *(const float4*)(Abase + (size_t)64 * QW_ + ac);
    float4 pb0 = *(const float4*)(Bn + ac);
    float4 pb1 = *(const float4*)(Bn + (size_t)64 * KVW_ + ac);

    for (int kt = 0; kt < 12; ++kt) {
        As[ac + 0][ar0]      = pa0.x;  As[ac + 1][ar0]      = pa0.y;
        As[ac + 2][ar0]      = pa0.z;  As[ac + 3][ar0]      = pa0.w;
        As[ac + 0][ar0 + 64] = pa1.x;  As[ac + 1][ar0 + 64] = pa1.y;
        As[ac + 2][ar0 + 64] = pa1.z;  As[ac + 3][ar0 + 64] = pa1.w;
        Bs[ac + 0][ar0]      = pb0.x;  Bs[ac + 1][ar0]      = pb0.y;
        Bs[ac + 2][ar0]      = pb0.z;  Bs[ac + 3][ar0]      = pb0.w;
        Bs[ac + 0][ar0 + 64] = pb1.x;  Bs[ac + 1][ar0 + 64] = pb1.y;
        Bs[ac + 2][ar0 + 64] = pb1.z;  Bs[ac + 3][ar0 + 64] = pb1.w;
        __syncthreads();

        if (kt + 1 < 12) {               // prefetch next tile
            const int k0 = (kt + 1) * 16;
            pa0 = *(const float4*)(Abase + k0 + ac);
            pa1 = *(const float4*)(Abase + (size_t)64 * QW_ + k0 + ac);
            if (k0 < DN_) {
                pb0 = *(const float4*)(Bn + k0 + ac);
                pb1 = *(const float4*)(Bn + (size_t)64 * KVW_ + k0 + ac);
            } else {
                pb0 = *(const float4*)(Bр + (k0 - DN_) + ac);
                pb1 = *(const float4*)(Bр + (size_t)64 * APAD_ + (k0 - DN_) + ac);
            }
        }

        #pragma unroll
        for (int k = 0; k < 16; ++k) {
            float4 av0 = *(const float4*)&As[k][ty * 8];
            float4 av1 = *(const float4*)&As[k][ty * 8 + 4];
            float4 bv0 = *(const float4*)&Bs[k][tx * 8];
            float4 bv1 = *(const float4*)&Bs[k][tx * 8 + 4];
            float aa[8] = {av0.x, av0.y, av0.z, av0.w, av1.x, av1.y, av1.z, av1.w};
            float bb[8] = {bv0.x, bv0.y, bv0.z, bv0.w, bv1.x, bv1.y, bv1.z, bv1.w};
            #pragma unroll
            for (int i = 0; i < 8; i++)
                #pragma unroll
                for (int j = 0; j < 8; j++) acc[i][j] += aa[i] * bb[j];
        }
        __syncthreads();
    }

    #pragma unroll
    for (int i = 0; i < 8; i++) {
        float* Cp = g_sc + ((size_t)h * S_ + sb * 128 + ty * 8 + i) * S_ + tb * 128 + tx * 8;
        *(float4*)Cp       = make_float4(acc[i][0], acc[i][1], acc[i][2], acc[i][3]);
        *(float4*)(Cp + 4) = make_float4(acc[i][4], acc[i][5], acc[i][6], acc[i][7]);
    }
}

// ------------------------------ row softmax ---------------------------------
// grid (S, H). Applies scale, zeroes t > s.
__global__ __launch_bounds__(256) void softmax_rows()
{
    const int s = blockIdx.x;
    const int h = blockIdx.y;
    float* row = g_sc + ((size_t)h * S_ + s) * S_;
    const int n = s + 1;
    const float scale = 0.07216878364870322f;  // 1/sqrt(192)
    __shared__ float red[256];
    const int tid = threadIdx.x;

    float m = -1e30f;
    for (int t = tid; t < n; t += 256) m = fmaxf(m, row[t]);
    red[tid] = m; __syncthreads();
    for (int o = 128; o > 0; o >>= 1) { if (tid < o) red[tid] = fmaxf(red[tid], red[tid + o]); __syncthreads(); }
    float rm = red[0];
    __syncthreads();

    float ssum = 0.0f;
    for (int t = tid; t < n; t += 256) {
        float e = __expf((row[t] - rm) * scale);
        row[t] = e;
        ssum += e;
    }
    red[tid] = ssum; __syncthreads();
    for (int o = 128; o > 0; o >>= 1) { if (tid < o) red[tid] += red[tid + o]; __syncthreads(); }
    float inv = 1.0f / red[0];

    for (int t = tid; t < n; t += 256) row[t] *= inv;
    for (int t = n + tid; t < S_; t += 256) row[t] = 0.0f;
}

// --------------------------- att = p @ v (causal) ---------------------------
// grid (1, S/128, H). N = 128, K limited to (sb+1)*128.
__global__ __launch_bounds__(256) void attn_pv()
{
    const int h = blockIdx.z;
    const int sb = blockIdx.y;

    __shared__ float As[16][128];
    __shared__ float Bs[16][128];
    const int tid = threadIdx.x;
    const int ty = tid >> 4, tx = tid & 15;
    const int ar0 = tid >> 2;
    const int ac  = (tid & 3) << 2;
    const int bk0 = tid >> 5;
    const int bc  = (tid & 31) << 2;

    float acc[8][8];
    #pragma unroll
    for (int i = 0; i < 8; i++)
        #pragma unroll
        for (int j = 0; j < 8; j++) acc[i][j] = 0.0f;

    const float* Ap = g_sc + (size_t)h * S_ * S_ + (size_t)(sb * 128 + ar0) * S_ + ac;
    const float* Bp = g_kv + (size_t)bk0 * KVW_ + h * (DN_ + DV_) + DN_ + bc;

    const int nk = (sb + 1) * 8;

    float4 pa0 = *(const float4*)(Ap);
    float4 pa1 = *(const float4*)(Ap + (size_t)64 * S_);
    float4 pb0 = *(const float4*)(Bp);
    float4 pb1 = *(const float4*)(Bp + (size_t)8 * KVW_);

    for (int kt = 0; kt < nk; ++kt) {
        As[ac + 0][ar0]      = pa0.x;  As[ac + 1][ar0]      = pa0.y;
        As[ac + 2][ar0]      = pa0.z;  As[ac + 3][ar0]      = pa0.w;
        As[ac + 0][ar0 + 64] = pa1.x;  As[ac + 1][ar0 + 64] = pa1.y;
        As[ac + 2][ar0 + 64] = pa1.z;  As[ac + 3][ar0 + 64] = pa1.w;
        *(float4*)&Bs[bk0][bc]     = pb0;
        *(float4*)&Bs[bk0 + 8][bc] = pb1;
        __syncthreads();

        if (kt + 1 < nk) {
            Ap += 16;
            Bp += (size_t)16 * KVW_;
            pa0 = *(const float4*)(Ap);
            pa1 = *(const float4*)(Ap + (size_t)64 * S_);
            pb0 = *(const float4*)(Bp);
            pb1 = *(const float4*)(Bp + (size_t)8 * KVW_);
        }

        #pragma unroll
        for (int k = 0; k < 16; ++k) {
            float4 av0 = *(const float4*)&As[k][ty * 8];
            float4 av1 = *(const float4*)&As[k][ty * 8 + 4];
            float4 bv0 = *(const float4*)&Bs[k][tx * 8];
            float4 bv1 = *(const float4*)&Bs[k][tx * 8 + 4];
            float aa[8] = {av0.x, av0.y, av0.z, av0.w, av1.x, av1.y, av1.z, av1.w};
            float bb[8] = {bv0.x, bv0.y, bv0.z, bv0.w, bv1.x, bv1.y, bv1.z, bv1.w};
            #pragma unroll
            for (int i = 0; i < 8; i++)
                #pragma unroll
                for (int j = 0; j < 8; j++) acc[i][j] += aa[i] * bb[j];
        }
        __syncthreads();
    }

    #pragma unroll
    for (int i = 0; i < 8; i++) {
        float* Cp = g_att + (size_t)(sb * 128 + ty * 8 + i) * (HEADS * DV_) + h * DV_ + tx * 8;
        *(float4*)Cp       = make_float4(acc[i][0], acc[i][1], acc[i][2], acc[i][3]);
        *(float4*)(Cp + 4) = make_float4(acc[i][4], acc[i][5], acc[i][6], acc[i][7]);
    }
}

// ------------------------------- launcher -----------------------------------
extern "C" void kernel_launch(void* const* d_in, const int* in_sizes, int n_in,
                              void* d_out, int out_size)
{
    const float* hidden = (const float*)d_in[0];
    const int*   pos    = (const int*)  d_in[1];
    const float* wfa    = (const float*)d_in[2];
    const float* gq     = (const float*)d_in[3];
    const float* gkv    = (const float*)d_in[4];
    const float* wqb    = (const float*)d_in[5];
    const float* wkvb   = (const float*)d_in[6];
    const float* wo     = (const float*)d_in[7];
    float* out = (float*)d_out;

    // device-symbol addresses resolved at module scope; kernels use globals
    // directly, but gemm128 is generic so get raw pointers once per launch.
    float *pwfa = nullptr, *pa = nullptr, *pq = nullptr, *pkv = nullptr, *patt = nullptr;
    cudaGetSymbolAddress((void**)&pwfa, g_wfa);
    cudaGetSymbolAddress((void**)&pa,   g_a);
    cudaGetSymbolAddress((void**)&pq,   g_q);
    cudaGetSymbolAddress((void**)&pkv,  g_kv);
    cudaGetSymbolAddress((void**)&patt, g_att);

    dim3 blk(256);

    // 0) pad weights
    pad_wfa<<<(HID_ * APAD_ + 255) / 256, 256>>>(wfa);
    // 1) a = hs @ w_fused_a
    gemm128<<<dim3(APAD_ / 128, S_ / 128), blk>>>(hidden, pwfa, pa, HID_, HID_, APAD_, APAD_);
    // 2) rmsnorms + k_pe rope
    norm_rope<<<S_, 256>>>(gq, gkv, pos);
    // 3) q = q_lat @ w_q_b
    gemm128<<<dim3(QW_ / 128, S_ / 128), blk>>>(pa, wqb, pq, QL_, APAD_, QW_, QW_);
    // 4) kv = ckv @ w_kv_b
    gemm128<<<dim3(KVW_ / 128, S_ / 128), blk>>>(pa + QL_, wkvb, pkv, KVL_, APAD_, KVW_, KVW_);
    // 5) q_pe rope
    rope_q<<<(S_ * HEADS * 32 + 255) / 256, 256>>>(pos);
    // 6) scores
    attn_scores<<<dim3(S_ / 128, S_ / 128, HEADS), blk>>>();
    // 7) softmax
    softmax_rows<<<dim3(S_, HEADS), 256>>>();
    // 8) att = p @ v
    attn_pv<<<dim3(1, S_ / 128, HEADS), blk>>>();
    // 9) out = att @ w_o
    gemm128<<<dim3(HID_ / 128, S_ / 128), blk>>>(patt, wo, out, HEADS * DV_, HEADS * DV_, HID_, HID_);
}

// round 4
// speedup vs baseline: 2.4441x; 2.4441x over previous
#include <cuda_runtime.h>
#include <cuda_bf16.h>
#include <math.h>
#include <stdint.h>

// ---------------------------------------------------------------------------
// MLA prefill — bf16 split-precision via mma.sync (plain sm_100 compatible).
//   All GEMMs: D = A · B^T, A [M,K] K-major rows, B [N,K] K-major rows.
//   bf16 hi/lo split: D += Ah·Bh + Ah·Bl + Al·Bh  (fp32 accumulate).
// ---------------------------------------------------------------------------

#define S_    2048
#define HID_  2048
#define HEADS 16
#define DN_   128
#define DR_   64
#define DV_   128
#define QL_   1536
#define KVL_  512
#define AW_   2112
#define APAD_ 2176
#define QW_   3072            // HEADS*(DN+DR)
#define KVW_  4096            // HEADS*(DN+DV)
#define DQK_  192             // DN+DR

typedef __nv_bfloat16 bf16;

// ------------------------------ fp32 scratch --------------------------------
__device__ float g_a  [(size_t)S_ * APAD_];
__device__ float g_q  [(size_t)S_ * QW_];
__device__ float g_kv [(size_t)S_ * KVW_];
__device__ float g_att[(size_t)S_ * HEADS * DV_];
__device__ float g_sc [(size_t)HEADS * S_ * S_];

// ------------------------------ bf16 hi/lo scratch ---------------------------
__device__ bf16 g_wfaTh[(size_t)APAD_ * HID_],  g_wfaTl[(size_t)APAD_ * HID_];
__device__ bf16 g_wqbTh[(size_t)QW_ * QL_],     g_wqbTl[(size_t)QW_ * QL_];
__device__ bf16 g_wkvTh[(size_t)KVW_ * KVL_],   g_wkvTl[(size_t)KVW_ * KVL_];
__device__ bf16 g_woTh [(size_t)HID_ * HID_],   g_woTl [(size_t)HID_ * HID_];
__device__ bf16 g_hsh  [(size_t)S_ * HID_],     g_hsl  [(size_t)S_ * HID_];
__device__ bf16 g_qlh  [(size_t)S_ * QL_],      g_qll  [(size_t)S_ * QL_];
__device__ bf16 g_ckvh [(size_t)S_ * KVL_],     g_ckvl [(size_t)S_ * KVL_];
__device__ bf16 g_qbh  [(size_t)HEADS * S_ * DQK_], g_qbl[(size_t)HEADS * S_ * DQK_];
__device__ bf16 g_kbh  [(size_t)HEADS * S_ * DQK_], g_kbl[(size_t)HEADS * S_ * DQK_];
__device__ bf16 g_vth  [(size_t)HEADS * DV_ * S_],  g_vtl[(size_t)HEADS * DV_ * S_];
__device__ bf16 g_pbh  [(size_t)HEADS * S_ * S_],   g_pbl[(size_t)HEADS * S_ * S_];
__device__ bf16 g_atbh [(size_t)S_ * HID_],     g_atbl[(size_t)S_ * HID_];

// ------------------------------ helpers -------------------------------------
__device__ __forceinline__ uint32_t smem_u32(const void* p) {
    uint32_t a;
    asm("{ .reg .u64 t; cvta.to.shared.u64 t, %1; cvt.u32.u64 %0, t; }"
        : "=r"(a) : "l"(p));
    return a;
}
__device__ __forceinline__ void splitbf(float x, bf16& h, bf16& l) {
    h = __float2bfloat16_rn(x);
    l = __float2bfloat16_rn(x - __bfloat162float(h));
}

#define LDX4(r, addr) \
    asm volatile("ldmatrix.sync.aligned.m8n8.x4.shared.b16 {%0,%1,%2,%3}, [%4];" \
        : "=r"((r)[0]), "=r"((r)[1]), "=r"((r)[2]), "=r"((r)[3]) : "r"(addr))

#define MMA(c, a, b0, b1) \
    asm volatile("mma.sync.aligned.m16n8k16.row.col.f32.bf16.bf16.f32 " \
        "{%0,%1,%2,%3}, {%4,%5,%6,%7}, {%8,%9}, {%0,%1,%2,%3};" \
        : "+f"((c)[0]), "+f"((c)[1]), "+f"((c)[2]), "+f"((c)[3]) \
        : "r"((a)[0]), "r"((a)[1]), "r"((a)[2]), "r"((a)[3]), "r"(b0), "r"(b1))

#define CP_ASYNC(sa, ga) \
    asm volatile("cp.async.cg.shared.global [%0], [%1], 16;" :: "r"(sa), "l"(ga))
#define CP_COMMIT() asm volatile("cp.async.commit_group;")

// ---------------- mma.sync split-bf16 GEMM, 128x128x64 ----------------------
// mode 0: plain. mode 1: scores (skip bx>by). mode 2: PV (nk=(by+1)*2).
// SMEM: double buffer x 4 tiles (Ah,Al,Bh,Bl) x 16 KB = 128 KB.
#define SMEM_GEMM 131072

__global__ __launch_bounds__(256) void gemm_mma(
    const bf16* __restrict__ Ah, const bf16* __restrict__ Al, long long sAb,
    const bf16* __restrict__ Bh, const bf16* __restrict__ Bl, long long sBb,
    float* __restrict__ C, long long sCb, int ldc,
    int K, int lda, int ldb, int mode)
{
    const int bx = blockIdx.x, by = blockIdx.y, bz = blockIdx.z;
    if (mode == 1 && bx > by) return;

    extern __shared__ bf16 smem_g[];
    const uint32_t sbase = smem_u32(smem_g);
    const int tid = threadIdx.x, wid = tid >> 5, lane = tid & 31;
    const int wm = (wid >> 1) * 32;        // warp m offset (4 rows of warps)
    const int wn = (wid & 1) * 64;         // warp n offset (2 cols of warps)

    Ah += (size_t)bz * sAb;  Al += (size_t)bz * sAb;
    Bh += (size_t)bz * sBb;  Bl += (size_t)bz * sBb;
    C  += (size_t)bz * sCb;

    const int m0 = by * 128, n0 = bx * 128;
    const int nk = (mode == 2) ? (by + 1) * 2 : (K >> 6);

    float acc[2][8][4];
    #pragma unroll
    for (int i = 0; i < 2; i++)
        #pragma unroll
        for (int j = 0; j < 8; j++)
            #pragma unroll
            for (int q = 0; q < 4; q++) acc[i][j][q] = 0.0f;

    // ---- async tile loader: 4 tiles of 128x64 bf16, XOR-swizzled ----
    auto issue_load = [&](int c, int b) {
        const bf16* srcs[4] = {Ah, Al, Bh, Bl};
        const int   lds [4] = {lda, lda, ldb, ldb};
        const int   r0s [4] = {m0, m0, n0, n0};
        const int k0 = c * 64;
        #pragma unroll
        for (int t = 0; t < 4; ++t) {
            uint32_t sdst = sbase + b * 65536 + t * 16384;
            const bf16* src = srcs[t] + (size_t)r0s[t] * lds[t] + k0;
            #pragma unroll
            for (int i = 0; i < 4; ++i) {
                int lin = tid + i * 256;
                int r = lin >> 3, ch = lin & 7;
                const bf16* g = src + (size_t)r * lds[t] + ch * 8;
                uint32_t so = sdst + r * 128 + ((ch ^ (r & 7)) << 4);
                CP_ASYNC(so, g);
            }
        }
        CP_COMMIT();
    };

    // ---- compute one 64-K chunk from buffer b ----
    auto compute = [&](int b) {
        const uint32_t aAh = sbase + b * 65536;
        const uint32_t aAl = aAh + 16384;
        const uint32_t aBh = aAh + 32768;
        const uint32_t aBl = aAh + 49152;
        #pragma unroll
        for (int ks = 0; ks < 4; ++ks) {
            uint32_t ah[2][4], al[2][4], bh[4][4], bl[4][4];
            // A frags: rr = wm + mf*16 + (lane&15), kk = ks*16 + (lane>>4)*8
            const int kkA = ks * 16 + (lane >> 4) * 8;
            #pragma unroll
            for (int mf = 0; mf < 2; ++mf) {
                int rr = wm + mf * 16 + (lane & 15);
                uint32_t off = rr * 128 + (((kkA >> 3) ^ (rr & 7)) << 4);
                LDX4(ah[mf], aAh + off);
                LDX4(al[mf], aAl + off);
            }
            // B frags: rr = wn + ng*16 + ((lane>>4)<<3) + (lane&7),
            //          kk = ks*16 + ((lane>>3)&1)*8
            const int kkB = ks * 16 + ((lane >> 3) & 1) * 8;
            #pragma unroll
            for (int ng = 0; ng < 4; ++ng) {
                int rr = wn + ng * 16 + ((lane >> 4) << 3) + (lane & 7);
                uint32_t off = rr * 128 + (((kkB >> 3) ^ (rr & 7)) << 4);
                LDX4(bh[ng], aBh + off);
                LDX4(bl[ng], aBl + off);
            }
            #pragma unroll
            for (int mf = 0; mf < 2; ++mf)
                #pragma unroll
                for (int nf = 0; nf < 8; ++nf) {
                    uint32_t b0 = bh[nf >> 1][(nf & 1) * 2];
                    uint32_t b1 = bh[nf >> 1][(nf & 1) * 2 + 1];
                    uint32_t c0 = bl[nf >> 1][(nf & 1) * 2];
                    uint32_t c1 = bl[nf >> 1][(nf & 1) * 2 + 1];
                    MMA(acc[mf][nf], ah[mf], b0, b1);   // hi*hi
                    MMA(acc[mf][nf], ah[mf], c0, c1);   // hi*lo
                    MMA(acc[mf][nf], al[mf], b0, b1);   // lo*hi
                }
        }
    };

    issue_load(0, 0);
    for (int c = 0; c < nk; ++c) {
        const int b = c & 1;
        if (c + 1 < nk) {
            issue_load(c + 1, b ^ 1);
            asm volatile("cp.async.wait_group 1;" ::: "memory");
        } else {
            asm volatile("cp.async.wait_group 0;" ::: "memory");
        }
        __syncthreads();
        compute(b);
        __syncthreads();
    }

    // ---- epilogue: fp32 stores ----
    #pragma unroll
    for (int mf = 0; mf < 2; ++mf)
        #pragma unroll
        for (int nf = 0; nf < 8; ++nf) {
            int r  = m0 + wm + mf * 16 + (lane >> 2);
            int cc = n0 + wn + nf * 8 + (lane & 3) * 2;
            float* p = C + (size_t)r * ldc + cc;
            *(float2*)p = make_float2(acc[mf][nf][0], acc[mf][nf][1]);
            float* p2 = p + (size_t)8 * ldc;
            *(float2*)p2 = make_float2(acc[mf][nf][2], acc[mf][nf][3]);
        }
}

// --------------- weight transpose + split: W[K,N] -> T[NP,K] bf16 -----------
__global__ void wconvT(const float* __restrict__ W, bf16* __restrict__ Th,
                       bf16* __restrict__ Tl, int K, int N)
{
    __shared__ float t[32][33];
    const int n0 = blockIdx.x * 32, k0 = blockIdx.y * 32;
    const int tx = threadIdx.x, ty = threadIdx.y;
    #pragma unroll
    for (int r = 0; r < 4; ++r) {
        int k = k0 + ty + r * 8, n = n0 + tx;
        t[ty + r * 8][tx] = (n < N) ? W[(size_t)k * N + n] : 0.0f;
    }
    __syncthreads();
    #pragma unroll
    for (int r = 0; r < 4; ++r) {
        int n = n0 + ty + r * 8, k = k0 + tx;
        bf16 h, l; splitbf(t[tx][ty + r * 8], h, l);
        Th[(size_t)n * K + k] = h;
        Tl[(size_t)n * K + k] = l;
    }
}

// ------------------- strided fp32 -> bf16 hi/lo convert ----------------------
__global__ void f2bf(const float* __restrict__ src, int ld, int cols,
                     bf16* __restrict__ h, bf16* __restrict__ l, int total)
{
    int idx = blockIdx.x * 256 + threadIdx.x;
    if (idx >= total) return;
    int r = idx / cols, c = idx - r * cols;
    bf16 hh, ll; splitbf(src[(size_t)r * ld + c], hh, ll);
    h[idx] = hh; l[idx] = ll;
}

// --------------------- rmsnorm(q_lat, ckv) + rope(k_pe) ---------------------
__global__ __launch_bounds__(256) void norm_rope(
    const float* __restrict__ gq, const float* __restrict__ gkv,
    const int* __restrict__ pos)
{
    const int s = blockIdx.x;
    float* row = g_a + (size_t)s * APAD_;
    __shared__ float red[256];
    const int tid = threadIdx.x;

    float ss = 0.0f;
    for (int i = tid; i < QL_; i += 256) { float v = row[i]; ss += v * v; }
    red[tid] = ss; __syncthreads();
    for (int o = 128; o > 0; o >>= 1) { if (tid < o) red[tid] += red[tid + o]; __syncthreads(); }
    __shared__ float rq_s;
    if (tid == 0) rq_s = rsqrtf(red[0] * (1.0f / QL_) + 1e-6f);
    __syncthreads();
    float rq = rq_s;
    for (int i = tid; i < QL_; i += 256) row[i] = row[i] * rq * gq[i];
    __syncthreads();

    ss = 0.0f;
    for (int i = tid; i < KVL_; i += 256) { float v = row[QL_ + i]; ss += v * v; }
    red[tid] = ss; __syncthreads();
    for (int o = 128; o > 0; o >>= 1) { if (tid < o) red[tid] += red[tid + o]; __syncthreads(); }
    __shared__ float rk_s;
    if (tid == 0) rk_s = rsqrtf(red[0] * (1.0f / KVL_) + 1e-6f);
    __syncthreads();
    float rk = rk_s;
    for (int i = tid; i < KVL_; i += 256) row[QL_ + i] = row[QL_ + i] * rk * gkv[i];

    if (tid < 32) {
        int i = tid;
        float inv = 1.0f / powf(10000.0f, (float)(2 * i) * (1.0f / 64.0f));
        float ang = (float)pos[s] * inv;
        float c, sn; sincosf(ang, &sn, &c);
        float x1 = row[QL_ + KVL_ + i];
        float x2 = row[QL_ + KVL_ + 32 + i];
        row[QL_ + KVL_ + i]      = x1 * c - x2 * sn;
        row[QL_ + KVL_ + 32 + i] = x2 * c + x1 * sn;
    }
}

// ------------------------------- rope(q_pe) ---------------------------------
__global__ void rope_q(const int* __restrict__ pos)
{
    int idx = blockIdx.x * 256 + threadIdx.x;
    if (idx >= S_ * HEADS * 32) return;
    int i = idx & 31;
    int h = (idx >> 5) & (HEADS - 1);
    int s = idx >> 9;
    size_t base = (size_t)s * QW_ + h * (DN_ + DR_) + DN_;
    float inv = 1.0f / powf(10000.0f, (float)(2 * i) * (1.0f / 64.0f));
    float ang = (float)pos[s] * inv;
    float c, sn; sincosf(ang, &sn, &c);
    float x1 = g_q[base + i], x2 = g_q[base + 32 + i];
    g_q[base + i]      = x1 * c - x2 * sn;
    g_q[base + 32 + i] = x2 * c + x1 * sn;
}

// -------------------- build qB/kB per-head K-major bf16 ----------------------
__global__ void qkprep()
{
    int idx = blockIdx.x * 256 + threadIdx.x;
    if (idx >= HEADS * S_ * DQK_) return;
    int d = idx % DQK_;
    int s = (idx / DQK_) & (S_ - 1);
    int h = idx / (DQK_ * S_);
    bf16 hh, ll;
    splitbf(g_q[(size_t)s * QW_ + h * DQK_ + d], hh, ll);
    g_qbh[idx] = hh; g_qbl[idx] = ll;
    float xk = (d < DN_) ? g_kv[(size_t)s * KVW_ + h * (DN_ + DV_) + d]
                         : g_a[(size_t)s * APAD_ + (QL_ + KVL_) + (d - DN_)];
    splitbf(xk, hh, ll);
    g_kbh[idx] = hh; g_kbl[idx] = ll;
}

// -------------------- vT[h][d][t] transpose + split --------------------------
__global__ void vtrans()
{
    __shared__ float t[32][33];
    const int h = blockIdx.z;
    const int t0 = blockIdx.x * 32, d0 = blockIdx.y * 32;
    const int tx = threadIdx.x, ty = threadIdx.y;
    #pragma unroll
    for (int r = 0; r < 4; ++r) {
        int tt = t0 + ty + r * 8;
        t[ty + r * 8][tx] = g_kv[(size_t)tt * KVW_ + h * (DN_ + DV_) + DN_ + d0 + tx];
    }
    __syncthreads();
    #pragma unroll
    for (int r = 0; r < 4; ++r) {
        int d = d0 + ty + r * 8, tt = t0 + tx;
        bf16 hh, ll; splitbf(t[tx][ty + r * 8], hh, ll);
        size_t o = ((size_t)h * DV_ + d) * S_ + tt;
        g_vth[o] = hh; g_vtl[o] = ll;
    }
}

// -------------------- softmax -> bf16 hi/lo probabilities --------------------
__global__ __launch_bounds__(256) void softmax_rows()
{
    const int s = blockIdx.x;
    const int h = blockIdx.y;
    float* row = g_sc + ((size_t)h * S_ + s) * S_;
    const int n = s + 1;
    const float scale = 0.07216878364870322f;  // 1/sqrt(192)
    __shared__ float red[256];
    const int tid = threadIdx.x;

    float m = -1e30f;
    for (int t = tid; t < n; t += 256) m = fmaxf(m, row[t]);
    red[tid] = m; __syncthreads();
    for (int o = 128; o > 0; o >>= 1) { if (tid < o) red[tid] = fmaxf(red[tid], red[tid + o]); __syncthreads(); }
    float rm = red[0];
    __syncthreads();

    float ssum = 0.0f;
    for (int t = tid; t < n; t += 256) {
        float e = __expf((row[t] - rm) * scale);
        row[t] = e;
        ssum += e;
    }
    red[tid] = ssum; __syncthreads();
    for (int o = 128; o > 0; o >>= 1) { if (tid < o) red[tid] += red[tid + o]; __syncthreads(); }
    float inv = 1.0f / red[0];

    size_t pb = ((size_t)h * S_ + s) * S_;
    for (int t = tid; t < n; t += 256) {
        bf16 hh, ll; splitbf(row[t] * inv, hh, ll);
        g_pbh[pb + t] = hh; g_pbl[pb + t] = ll;
    }
    bf16 z = __float2bfloat16_rn(0.0f);
    for (int t = n + tid; t < S_; t += 256) { g_pbh[pb + t] = z; g_pbl[pb + t] = z; }
}

// ------------------------------- launcher -----------------------------------
extern "C" void kernel_launch(void* const* d_in, const int* in_sizes, int n_in,
                              void* d_out, int out_size)
{
    const float* hidden = (const float*)d_in[0];
    const int*   pos    = (const int*)  d_in[1];
    const float* wfa    = (const float*)d_in[2];
    const float* gq     = (const float*)d_in[3];
    const float* gkv    = (const float*)d_in[4];
    const float* wqb    = (const float*)d_in[5];
    const float* wkvb   = (const float*)d_in[6];
    const float* wo     = (const float*)d_in[7];
    float* out = (float*)d_out;

    cudaFuncSetAttribute(gemm_mma, cudaFuncAttributeMaxDynamicSharedMemorySize,
                         SMEM_GEMM);

    #define SYM(p, s) cudaGetSymbolAddress((void**)&p, s)
    float *pa, *pq, *pkv, *patt, *psc;
    bf16 *wfaTh, *wfaTl, *wqbTh, *wqbTl, *wkvTh, *wkvTl, *woTh, *woTl;
    bf16 *hsh, *hsl, *qlh, *qll, *ckvh, *ckvl;
    bf16 *qbh, *qbl, *kbh, *kbl, *vth, *vtl, *pbh, *pbl, *atbh, *atbl;
    SYM(pa, g_a); SYM(pq, g_q); SYM(pkv, g_kv); SYM(patt, g_att); SYM(psc, g_sc);
    SYM(wfaTh, g_wfaTh); SYM(wfaTl, g_wfaTl);
    SYM(wqbTh, g_wqbTh); SYM(wqbTl, g_wqbTl);
    SYM(wkvTh, g_wkvTh); SYM(wkvTl, g_wkvTl);
    SYM(woTh, g_woTh);   SYM(woTl, g_woTl);
    SYM(hsh, g_hsh); SYM(hsl, g_hsl);
    SYM(qlh, g_qlh); SYM(qll, g_qll);
    SYM(ckvh, g_ckvh); SYM(ckvl, g_ckvl);
    SYM(qbh, g_qbh); SYM(qbl, g_qbl);
    SYM(kbh, g_kbh); SYM(kbl, g_kbl);
    SYM(vth, g_vth); SYM(vtl, g_vtl);
    SYM(pbh, g_pbh); SYM(pbl, g_pbl);
    SYM(atbh, g_atbh); SYM(atbl, g_atbl);
    #undef SYM

    dim3 tb(32, 8);

    // weight transpose + hi/lo split
    wconvT<<<dim3(APAD_ / 32, HID_ / 32), tb>>>(wfa, wfaTh, wfaTl, HID_, AW_);
    wconvT<<<dim3(QW_ / 32, QL_ / 32), tb>>>(wqb, wqbTh, wqbTl, QL_, QW_);
    wconvT<<<dim3(KVW_ / 32, KVL_ / 32), tb>>>(wkvb, wkvTh, wkvTl, KVL_, KVW_);
    wconvT<<<dim3(HID_ / 32, HID_ / 32), tb>>>(wo, woTh, woTl, HID_, HID_);

    // hidden -> bf16 split
    f2bf<<<(S_ * HID_ + 255) / 256, 256>>>(hidden, HID_, HID_, hsh, hsl, S_ * HID_);

    // GEMM1: a = hs @ wfa   [2048 x 2176], K=2048
    gemm_mma<<<dim3(APAD_ / 128, S_ / 128, 1), 256, SMEM_GEMM>>>(
        hsh, hsl, 0, wfaTh, wfaTl, 0, pa, 0, APAD_, HID_, HID_, HID_, 0);

    norm_rope<<<S_, 256>>>(gq, gkv, pos);

    f2bf<<<(S_ * QL_ + 255) / 256, 256>>>(pa, APAD_, QL_, qlh, qll, S_ * QL_);
    f2bf<<<(S_ * KVL_ + 255) / 256, 256>>>(pa + QL_, APAD_, KVL_, ckvh, ckvl, S_ * KVL_);

    // GEMM2: q = qlat @ wqb  [2048 x 3072], K=1536
    gemm_mma<<<dim3(QW_ / 128, S_ / 128, 1), 256, SMEM_GEMM>>>(
        qlh, qll, 0, wqbTh, wqbTl, 0, pq, 0, QW_, QL_, QL_, QL_, 0);
    // GEMM3: kv = ckv @ wkvb [2048 x 4096], K=512
    gemm_mma<<<dim3(KVW_ / 128, S_ / 128, 1), 256, SMEM_GEMM>>>(
        ckvh, ckvl, 0, wkvTh, wkvTl, 0, pkv, 0, KVW_, KVL_, KVL_, KVL_, 0);

    rope_q<<<(S_ * HEADS * 32 + 255) / 256, 256>>>(pos);

    qkprep<<<(HEADS * S_ * DQK_ + 255) / 256, 256>>>();
    vtrans<<<dim3(S_ / 32, DV_ / 32, HEADS), tb>>>();

    // scores: per head, causal skip; K=192 (3 chunks of 64)
    gemm_mma<<<dim3(S_ / 128, S_ / 128, HEADS), 256, SMEM_GEMM>>>(
        qbh, qbl, (long long)S_ * DQK_, kbh, kbl, (long long)S_ * DQK_,
        psc, (long long)S_ * S_, S_, DQK_, DQK_, DQK_, 1);

    softmax_rows<<<dim3(S_, HEADS), 256>>>();

    // PV: per head, K limited causally
    gemm_mma<<<dim3(1, S_ / 128, HEADS), 256, SMEM_GEMM>>>(
        pbh, pbl, (long long)S_ * S_, vth, vtl, (long long)DV_ * S_,
        patt, (long long)DV_, HEADS * DV_, S_, S_, S_, 2);

    f2bf<<<(S_ * HID_ + 255) / 256, 256>>>(patt, HID_, HID_, atbh, atbl, S_ * HID_);

    // GEMM4: out = att @ wo  [2048 x 2048], K=2048
    gemm_mma<<<dim3(HID_ / 128, S_ / 128, 1), 256, SMEM_GEMM>>>(
        atbh, atbl, 0, woTh, woTl, 0, out, 0, HID_, HID_, HID_, HID_, 0);
}

// round 5
// speedup vs baseline: 2.4778x; 1.0138x over previous
#include <cuda_runtime.h>
#include <cuda_bf16.h>
#include <math.h>
#include <stdint.h>

// ---------------------------------------------------------------------------
// MLA prefill — bf16 split-precision via mma.sync (plain sm_100 compatible).
//   All GEMMs: D = A · B^T, A [M,K] K-major rows, B [N,K] K-major rows.
//   bf16 hi/lo split: D += Ah·Bh + Ah·Bl + Al·Bh  (fp32 accumulate).
//   R5: pipelined ldmatrix/MMA, fused bf16 conversions, trimmed zero-fill.
// ---------------------------------------------------------------------------

#define S_    2048
#define HID_  2048
#define HEADS 16
#define DN_   128
#define DR_   64
#define DV_   128
#define QL_   1536
#define KVL_  512
#define AW_   2112
#define APAD_ 2176
#define QW_   3072            // HEADS*(DN+DR)
#define KVW_  4096            // HEADS*(DN+DV)
#define DQK_  192             // DN+DR

typedef __nv_bfloat16 bf16;

// ------------------------------ fp32 scratch --------------------------------
__device__ float g_a  [(size_t)S_ * APAD_];
__device__ float g_q  [(size_t)S_ * QW_];
__device__ float g_kv [(size_t)S_ * KVW_];
__device__ float g_sc [(size_t)HEADS * S_ * S_];

// ------------------------------ bf16 hi/lo scratch ---------------------------
__device__ bf16 g_wfaTh[(size_t)APAD_ * HID_],  g_wfaTl[(size_t)APAD_ * HID_];
__device__ bf16 g_wqbTh[(size_t)QW_ * QL_],     g_wqbTl[(size_t)QW_ * QL_];
__device__ bf16 g_wkvTh[(size_t)KVW_ * KVL_],   g_wkvTl[(size_t)KVW_ * KVL_];
__device__ bf16 g_woTh [(size_t)HID_ * HID_],   g_woTl [(size_t)HID_ * HID_];
__device__ bf16 g_hsh  [(size_t)S_ * HID_],     g_hsl  [(size_t)S_ * HID_];
__device__ bf16 g_qlh  [(size_t)S_ * QL_],      g_qll  [(size_t)S_ * QL_];
__device__ bf16 g_ckvh [(size_t)S_ * KVL_],     g_ckvl [(size_t)S_ * KVL_];
__device__ bf16 g_qbh  [(size_t)HEADS * S_ * DQK_], g_qbl[(size_t)HEADS * S_ * DQK_];
__device__ bf16 g_kbh  [(size_t)HEADS * S_ * DQK_], g_kbl[(size_t)HEADS * S_ * DQK_];
__device__ bf16 g_vth  [(size_t)HEADS * DV_ * S_],  g_vtl[(size_t)HEADS * DV_ * S_];
__device__ bf16 g_pbh  [(size_t)HEADS * S_ * S_],   g_pbl[(size_t)HEADS * S_ * S_];
__device__ bf16 g_atbh [(size_t)S_ * HID_],     g_atbl[(size_t)S_ * HID_];

// ------------------------------ helpers -------------------------------------
__device__ __forceinline__ uint32_t smem_u32(const void* p) {
    uint32_t a;
    asm("{ .reg .u64 t; cvta.to.shared.u64 t, %1; cvt.u32.u64 %0, t; }"
        : "=r"(a) : "l"(p));
    return a;
}
__device__ __forceinline__ void splitbf(float x, bf16& h, bf16& l) {
    h = __float2bfloat16_rn(x);
    l = __float2bfloat16_rn(x - __bfloat162float(h));
}

#define LDX4(r, addr) \
    asm volatile("ldmatrix.sync.aligned.m8n8.x4.shared.b16 {%0,%1,%2,%3}, [%4];" \
        : "=r"((r)[0]), "=r"((r)[1]), "=r"((r)[2]), "=r"((r)[3]) : "r"(addr))

#define MMA(c, a, b0, b1) \
    asm volatile("mma.sync.aligned.m16n8k16.row.col.f32.bf16.bf16.f32 " \
        "{%0,%1,%2,%3}, {%4,%5,%6,%7}, {%8,%9}, {%0,%1,%2,%3};" \
        : "+f"((c)[0]), "+f"((c)[1]), "+f"((c)[2]), "+f"((c)[3]) \
        : "r"((a)[0]), "r"((a)[1]), "r"((a)[2]), "r"((a)[3]), "r"(b0), "r"(b1))

#define CP_ASYNC(sa, ga) \
    asm volatile("cp.async.cg.shared.global [%0], [%1], 16;" :: "r"(sa), "l"(ga))
#define CP_COMMIT() asm volatile("cp.async.commit_group;")

// ---------------- mma.sync split-bf16 GEMM, 128x128x64 ----------------------
// mode 0: plain. mode 1: scores (skip bx>by). mode 2: PV (nk=(by+1)*2).
// omode 0: fp32 C. omode 1: bf16 hi/lo split to Ch/Cl.
#define SMEM_GEMM 131072

__global__ __launch_bounds__(256) void gemm_mma(
    const bf16* __restrict__ Ah, const bf16* __restrict__ Al, long long sAb,
    const bf16* __restrict__ Bh, const bf16* __restrict__ Bl, long long sBb,
    float* __restrict__ C, bf16* __restrict__ Ch, bf16* __restrict__ Cl,
    long long sCb, int ldc,
    int K, int lda, int ldb, int mode, int omode)
{
    const int bx = blockIdx.x, by = blockIdx.y, bz = blockIdx.z;
    if (mode == 1 && bx > by) return;

    extern __shared__ bf16 smem_g[];
    const uint32_t sbase = smem_u32(smem_g);
    const int tid = threadIdx.x, wid = tid >> 5, lane = tid & 31;
    const int wm = (wid >> 1) * 32;
    const int wn = (wid & 1) * 64;

    Ah += (size_t)bz * sAb;  Al += (size_t)bz * sAb;
    Bh += (size_t)bz * sBb;  Bl += (size_t)bz * sBb;

    const int m0 = by * 128, n0 = bx * 128;
    const int nk = (mode == 2) ? (by + 1) * 2 : (K >> 6);

    float acc[2][8][4];
    #pragma unroll
    for (int i = 0; i < 2; i++)
        #pragma unroll
        for (int j = 0; j < 8; j++)
            #pragma unroll
            for (int q = 0; q < 4; q++) acc[i][j][q] = 0.0f;

    auto issue_load = [&](int c, int b) {
        const bf16* srcs[4] = {Ah, Al, Bh, Bl};
        const int   lds [4] = {lda, lda, ldb, ldb};
        const int   r0s [4] = {m0, m0, n0, n0};
        const int k0 = c * 64;
        #pragma unroll
        for (int t = 0; t < 4; ++t) {
            uint32_t sdst = sbase + b * 65536 + t * 16384;
            const bf16* src = srcs[t] + (size_t)r0s[t] * lds[t] + k0;
            #pragma unroll
            for (int i = 0; i < 4; ++i) {
                int lin = tid + i * 256;
                int r = lin >> 3, ch = lin & 7;
                const bf16* g = src + (size_t)r * lds[t] + ch * 8;
                uint32_t so = sdst + r * 128 + ((ch ^ (r & 7)) << 4);
                CP_ASYNC(so, g);
            }
        }
        CP_COMMIT();
    };

    // pipelined compute on buffer b: frags double-buffered across k-steps
    auto compute = [&](int b) {
        const uint32_t aAh = sbase + b * 65536;
        const uint32_t aAl = aAh + 16384;
        const uint32_t aBh = aAh + 32768;
        const uint32_t aBl = aAh + 49152;
        uint32_t ah[2][2][4], al[2][2][4], bh[2][4][4], bl[2][4][4];

        auto ldf = [&](int ks, int p) {
            const int kkA = ks * 16 + (lane >> 4) * 8;
            #pragma unroll
            for (int mf = 0; mf < 2; ++mf) {
                int rr = wm + mf * 16 + (lane & 15);
                uint32_t off = rr * 128 + (((kkA >> 3) ^ (rr & 7)) << 4);
                LDX4(ah[p][mf], aAh + off);
                LDX4(al[p][mf], aAl + off);
            }
            const int kkB = ks * 16 + ((lane >> 3) & 1) * 8;
            #pragma unroll
            for (int ng = 0; ng < 4; ++ng) {
                int rr = wn + ng * 16 + ((lane >> 4) << 3) + (lane & 7);
                uint32_t off = rr * 128 + (((kkB >> 3) ^ (rr & 7)) << 4);
                LDX4(bh[p][ng], aBh + off);
                LDX4(bl[p][ng], aBl + off);
            }
        };

        ldf(0, 0);
        #pragma unroll
        for (int ks = 0; ks < 4; ++ks) {
            const int cur = ks & 1;
            if (ks < 3) ldf(ks + 1, cur ^ 1);
            #pragma unroll
            for (int mf = 0; mf < 2; ++mf)
                #pragma unroll
                for (int nf = 0; nf < 8; ++nf) {
                    uint32_t b0 = bh[cur][nf >> 1][(nf & 1) * 2];
                    uint32_t b1 = bh[cur][nf >> 1][(nf & 1) * 2 + 1];
                    uint32_t c0 = bl[cur][nf >> 1][(nf & 1) * 2];
                    uint32_t c1 = bl[cur][nf >> 1][(nf & 1) * 2 + 1];
                    MMA(acc[mf][nf], ah[cur][mf], b0, b1);   // hi*hi
                    MMA(acc[mf][nf], ah[cur][mf], c0, c1);   // hi*lo
                    MMA(acc[mf][nf], al[cur][mf], b0, b1);   // lo*hi
                }
        }
    };

    issue_load(0, 0);
    for (int c = 0; c < nk; ++c) {
        const int b = c & 1;
        if (c + 1 < nk) {
            issue_load(c + 1, b ^ 1);
            asm volatile("cp.async.wait_group 1;" ::: "memory");
        } else {
            asm volatile("cp.async.wait_group 0;" ::: "memory");
        }
        __syncthreads();
        compute(b);
        __syncthreads();
    }

    // ---- epilogue ----
    if (omode == 0) {
        float* Co = C + (size_t)bz * sCb;
        #pragma unroll
        for (int mf = 0; mf < 2; ++mf)
            #pragma unroll
            for (int nf = 0; nf < 8; ++nf) {
                int r  = m0 + wm + mf * 16 + (lane >> 2);
                int cc = n0 + wn + nf * 8 + (lane & 3) * 2;
                float* p = Co + (size_t)r * ldc + cc;
                *(float2*)p = make_float2(acc[mf][nf][0], acc[mf][nf][1]);
                float* p2 = p + (size_t)8 * ldc;
                *(float2*)p2 = make_float2(acc[mf][nf][2], acc[mf][nf][3]);
            }
    } else {
        bf16* Cho = Ch + (size_t)bz * sCb;
        bf16* Clo = Cl + (size_t)bz * sCb;
        #pragma unroll
        for (int mf = 0; mf < 2; ++mf)
            #pragma unroll
            for (int nf = 0; nf < 8; ++nf) {
                int r  = m0 + wm + mf * 16 + (lane >> 2);
                int cc = n0 + wn + nf * 8 + (lane & 3) * 2;
                bf16 h0, l0, h1, l1;
                splitbf(acc[mf][nf][0], h0, l0);
                splitbf(acc[mf][nf][1], h1, l1);
                *(__nv_bfloat162*)(Cho + (size_t)r * ldc + cc) = __nv_bfloat162(h0, h1);
                *(__nv_bfloat162*)(Clo + (size_t)r * ldc + cc) = __nv_bfloat162(l0, l1);
                splitbf(acc[mf][nf][2], h0, l0);
                splitbf(acc[mf][nf][3], h1, l1);
                *(__nv_bfloat162*)(Cho + (size_t)(r + 8) * ldc + cc) = __nv_bfloat162(h0, h1);
                *(__nv_bfloat162*)(Clo + (size_t)(r + 8) * ldc + cc) = __nv_bfloat162(l0, l1);
            }
    }
}

// --------------- weight transpose + split: W[K,N] -> T[NP,K] bf16 -----------
__global__ void wconvT(const float* __restrict__ W, bf16* __restrict__ Th,
                       bf16* __restrict__ Tl, int K, int N)
{
    __shared__ float t[32][33];
    const int n0 = blockIdx.x * 32, k0 = blockIdx.y * 32;
    const int tx = threadIdx.x, ty = threadIdx.y;
    #pragma unroll
    for (int r = 0; r < 4; ++r) {
        int k = k0 + ty + r * 8, n = n0 + tx;
        t[ty + r * 8][tx] = (n < N) ? W[(size_t)k * N + n] : 0.0f;
    }
    __syncthreads();
    #pragma unroll
    for (int r = 0; r < 4; ++r) {
        int n = n0 + ty + r * 8, k = k0 + tx;
        bf16 h, l; splitbf(t[tx][ty + r * 8], h, l);
        Th[(size_t)n * K + k] = h;
        Tl[(size_t)n * K + k] = l;
    }
}

// ------------------- fp32 -> bf16 hi/lo convert ------------------------------
__global__ void f2bf(const float* __restrict__ src, int ld, int cols,
                     bf16* __restrict__ h, bf16* __restrict__ l, int total)
{
    int idx = blockIdx.x * 256 + threadIdx.x;
    if (idx >= total) return;
    int r = idx / cols, c = idx - r * cols;
    bf16 hh, ll; splitbf(src[(size_t)r * ld + c], hh, ll);
    h[idx] = hh; l[idx] = ll;
}

// --------- rmsnorm(q_lat, ckv) -> bf16 hi/lo + rope(k_pe) fp32 ---------------
__global__ __launch_bounds__(256) void norm_rope(
    const float* __restrict__ gq, const float* __restrict__ gkv,
    const int* __restrict__ pos)
{
    const int s = blockIdx.x;
    float* row = g_a + (size_t)s * APAD_;
    __shared__ float red[256];
    const int tid = threadIdx.x;

    float ss = 0.0f;
    for (int i = tid; i < QL_; i += 256) { float v = row[i]; ss += v * v; }
    red[tid] = ss; __syncthreads();
    for (int o = 128; o > 0; o >>= 1) { if (tid < o) red[tid] += red[tid + o]; __syncthreads(); }
    __shared__ float rq_s;
    if (tid == 0) rq_s = rsqrtf(red[0] * (1.0f / QL_) + 1e-6f);
    __syncthreads();
    float rq = rq_s;
    for (int i = tid; i < QL_; i += 256) {
        bf16 hh, ll; splitbf(row[i] * rq * gq[i], hh, ll);
        g_qlh[(size_t)s * QL_ + i] = hh;
        g_qll[(size_t)s * QL_ + i] = ll;
    }
    __syncthreads();

    ss = 0.0f;
    for (int i = tid; i < KVL_; i += 256) { float v = row[QL_ + i]; ss += v * v; }
    red[tid] = ss; __syncthreads();
    for (int o = 128; o > 0; o >>= 1) { if (tid < o) red[tid] += red[tid + o]; __syncthreads(); }
    __shared__ float rk_s;
    if (tid == 0) rk_s = rsqrtf(red[0] * (1.0f / KVL_) + 1e-6f);
    __syncthreads();
    float rk = rk_s;
    for (int i = tid; i < KVL_; i += 256) {
        bf16 hh, ll; splitbf(row[QL_ + i] * rk * gkv[i], hh, ll);
        g_ckvh[(size_t)s * KVL_ + i] = hh;
        g_ckvl[(size_t)s * KVL_ + i] = ll;
    }

    if (tid < 32) {
        int i = tid;
        float inv = 1.0f / powf(10000.0f, (float)(2 * i) * (1.0f / 64.0f));
        float ang = (float)pos[s] * inv;
        float c, sn; sincosf(ang, &sn, &c);
        float x1 = row[QL_ + KVL_ + i];
        float x2 = row[QL_ + KVL_ + 32 + i];
        row[QL_ + KVL_ + i]      = x1 * c - x2 * sn;
        row[QL_ + KVL_ + 32 + i] = x2 * c + x1 * sn;
    }
}

// ------------------------------- rope(q_pe) ---------------------------------
__global__ void rope_q(const int* __restrict__ pos)
{
    int idx = blockIdx.x * 256 + threadIdx.x;
    if (idx >= S_ * HEADS * 32) return;
    int i = idx & 31;
    int h = (idx >> 5) & (HEADS - 1);
    int s = idx >> 9;
    size_t base = (size_t)s * QW_ + h * (DN_ + DR_) + DN_;
    float inv = 1.0f / powf(10000.0f, (float)(2 * i) * (1.0f / 64.0f));
    float ang = (float)pos[s] * inv;
    float c, sn; sincosf(ang, &sn, &c);
    float x1 = g_q[base + i], x2 = g_q[base + 32 + i];
    g_q[base + i]      = x1 * c - x2 * sn;
    g_q[base + 32 + i] = x2 * c + x1 * sn;
}

// -------------------- build qB/kB per-head K-major bf16 ----------------------
__global__ void qkprep()
{
    int idx = blockIdx.x * 256 + threadIdx.x;
    if (idx >= HEADS * S_ * DQK_) return;
    int d = idx % DQK_;
    int s = (idx / DQK_) & (S_ - 1);
    int h = idx / (DQK_ * S_);
    bf16 hh, ll;
    splitbf(g_q[(size_t)s * QW_ + h * DQK_ + d], hh, ll);
    g_qbh[idx] = hh; g_qbl[idx] = ll;
    float xk = (d < DN_) ? g_kv[(size_t)s * KVW_ + h * (DN_ + DV_) + d]
                         : g_a[(size_t)s * APAD_ + (QL_ + KVL_) + (d - DN_)];
    splitbf(xk, hh, ll);
    g_kbh[idx] = hh; g_kbl[idx] = ll;
}

// -------------------- vT[h][d][t] transpose + split --------------------------
__global__ void vtrans()
{
    __shared__ float t[32][33];
    const int h = blockIdx.z;
    const int t0 = blockIdx.x * 32, d0 = blockIdx.y * 32;
    const int tx = threadIdx.x, ty = threadIdx.y;
    #pragma unroll
    for (int r = 0; r < 4; ++r) {
        int tt = t0 + ty + r * 8;
        t[ty + r * 8][tx] = g_kv[(size_t)tt * KVW_ + h * (DN_ + DV_) + DN_ + d0 + tx];
    }
    __syncthreads();
    #pragma unroll
    for (int r = 0; r < 4; ++r) {
        int d = d0 + ty + r * 8, tt = t0 + tx;
        bf16 hh, ll; splitbf(t[tx][ty + r * 8], hh, ll);
        size_t o = ((size_t)h * DV_ + d) * S_ + tt;
        g_vth[o] = hh; g_vtl[o] = ll;
    }
}

// -------------------- softmax -> bf16 hi/lo probabilities --------------------
__global__ __launch_bounds__(256) void softmax_rows()
{
    const int s = blockIdx.x;
    const int h = blockIdx.y;
    float* row = g_sc + ((size_t)h * S_ + s) * S_;
    const int n = s + 1;
    const float scale = 0.07216878364870322f;  // 1/sqrt(192)
    __shared__ float red[256];
    const int tid = threadIdx.x;

    float m = -1e30f;
    for (int t = tid; t < n; t += 256) m = fmaxf(m, row[t]);
    red[tid] = m; __syncthreads();
    for (int o = 128; o > 0; o >>= 1) { if (tid < o) red[tid] = fmaxf(red[tid], red[tid + o]); __syncthreads(); }
    float rm = red[0];
    __syncthreads();

    float ssum = 0.0f;
    for (int t = tid; t < n; t += 256) {
        float e = __expf((row[t] - rm) * scale);
        row[t] = e;
        ssum += e;
    }
    red[tid] = ssum; __syncthreads();
    for (int o = 128; o > 0; o >>= 1) { if (tid < o) red[tid] += red[tid + o]; __syncthreads(); }
    float inv = 1.0f / red[0];

    size_t pb = ((size_t)h * S_ + s) * S_;
    for (int t = tid; t < n; t += 256) {
        bf16 hh, ll; splitbf(row[t] * inv, hh, ll);
        g_pbh[pb + t] = hh; g_pbl[pb + t] = ll;
    }
    // zeros only needed through the end of the diagonal 128-block (PV never
    // reads past (by+1)*128 columns).
    const int nz = (n + 127) & ~127;
    bf16 z = __float2bfloat16_rn(0.0f);
    for (int t = n + tid; t < nz; t += 256) { g_pbh[pb + t] = z; g_pbl[pb + t] = z; }
}

// ------------------------------- launcher -----------------------------------
extern "C" void kernel_launch(void* const* d_in, const int* in_sizes, int n_in,
                              void* d_out, int out_size)
{
    const float* hidden = (const float*)d_in[0];
    const int*   pos    = (const int*)  d_in[1];
    const float* wfa    = (const float*)d_in[2];
    const float* gq     = (const float*)d_in[3];
    const float* gkv    = (const float*)d_in[4];
    const float* wqb    = (const float*)d_in[5];
    const float* wkvb   = (const float*)d_in[6];
    const float* wo     = (const float*)d_in[7];
    float* out = (float*)d_out;

    cudaFuncSetAttribute(gemm_mma, cudaFuncAttributeMaxDynamicSharedMemorySize,
                         SMEM_GEMM);

    #define SYM(p, s) cudaGetSymbolAddress((void**)&p, s)
    float *pa, *pq, *pkv, *psc;
    bf16 *wfaTh, *wfaTl, *wqbTh, *wqbTl, *wkvTh, *wkvTl, *woTh, *woTl;
    bf16 *hsh, *hsl, *qlh, *qll, *ckvh, *ckvl;
    bf16 *qbh, *qbl, *kbh, *kbl, *vth, *vtl, *pbh, *pbl, *atbh, *atbl;
    SYM(pa, g_a); SYM(pq, g_q); SYM(pkv, g_kv); SYM(psc, g_sc);
    SYM(wfaTh, g_wfaTh); SYM(wfaTl, g_wfaTl);
    SYM(wqbTh, g_wqbTh); SYM(wqbTl, g_wqbTl);
    SYM(wkvTh, g_wkvTh); SYM(wkvTl, g_wkvTl);
    SYM(woTh, g_woTh);   SYM(woTl, g_woTl);
    SYM(hsh, g_hsh); SYM(hsl, g_hsl);
    SYM(qlh, g_qlh); SYM(qll, g_qll);
    SYM(ckvh, g_ckvh); SYM(ckvl, g_ckvl);
    SYM(qbh, g_qbh); SYM(qbl, g_qbl);
    SYM(kbh, g_kbh); SYM(kbl, g_kbl);
    SYM(vth, g_vth); SYM(vtl, g_vtl);
    SYM(pbh, g_pbh); SYM(pbl, g_pbl);
    SYM(atbh, g_atbh); SYM(atbl, g_atbl);
    #undef SYM

    dim3 tb(32, 8);

    // launch order keeps gemm1 at position 4 for profiler visibility
    wconvT<<<dim3(APAD_ / 32, HID_ / 32), tb>>>(wfa, wfaTh, wfaTl, HID_, AW_);   // 1
    f2bf<<<(S_ * HID_ + 255) / 256, 256>>>(hidden, HID_, HID_, hsh, hsl, S_ * HID_); // 2
    wconvT<<<dim3(QW_ / 32, QL_ / 32), tb>>>(wqb, wqbTh, wqbTl, QL_, QW_);       // 3

    // 4) GEMM1: a = hs @ wfa   [2048 x 2176], K=2048
    gemm_mma<<<dim3(APAD_ / 128, S_ / 128, 1), 256, SMEM_GEMM>>>(
        hsh, hsl, 0, wfaTh, wfaTl, 0, pa, nullptr, nullptr, 0, APAD_,
        HID_, HID_, HID_, 0, 0);

    norm_rope<<<S_, 256>>>(gq, gkv, pos);                                        // 5
    wconvT<<<dim3(KVW_ / 32, KVL_ / 32), tb>>>(wkvb, wkvTh, wkvTl, KVL_, KVW_);  // 6

    // 7) GEMM2: q = qlat @ wqb  [2048 x 3072], K=1536
    gemm_mma<<<dim3(QW_ / 128, S_ / 128, 1), 256, SMEM_GEMM>>>(
        qlh, qll, 0, wqbTh, wqbTl, 0, pq, nullptr, nullptr, 0, QW_,
        QL_, QL_, QL_, 0, 0);

    wconvT<<<dim3(HID_ / 32, HID_ / 32), tb>>>(wo, woTh, woTl, HID_, HID_);      // 8

    // 9) GEMM3: kv = ckv @ wkvb [2048 x 4096], K=512
    gemm_mma<<<dim3(KVW_ / 128, S_ / 128, 1), 256, SMEM_GEMM>>>(
        ckvh, ckvl, 0, wkvTh, wkvTl, 0, pkv, nullptr, nullptr, 0, KVW_,
        KVL_, KVL_, KVL_, 0, 0);

    rope_q<<<(S_ * HEADS * 32 + 255) / 256, 256>>>(pos);                         // 10
    qkprep<<<(HEADS * S_ * DQK_ + 255) / 256, 256>>>();                          // 11
    vtrans<<<dim3(S_ / 32, DV_ / 32, HEADS), tb>>>();                            // 12

    // 13) scores: per head, causal skip; K=192 (3 chunks of 64)
    gemm_mma<<<dim3(S_ / 128, S_ / 128, HEADS), 256, SMEM_GEMM>>>(
        qbh, qbl, (long long)S_ * DQK_, kbh, kbl, (long long)S_ * DQK_,
        psc, nullptr, nullptr, (long long)S_ * S_, S_,
        DQK_, DQK_, DQK_, 1, 0);

    softmax_rows<<<dim3(S_, HEADS), 256>>>();                                    // 14

    // 15) PV: per head, K limited causally; bf16 split epilogue -> atbh/atbl
    gemm_mma<<<dim3(1, S_ / 128, HEADS), 256, SMEM_GEMM>>>(
        pbh, pbl, (long long)S_ * S_, vth, vtl, (long long)DV_ * S_,
        nullptr, atbh, atbl, (long long)DV_, HEADS * DV_,
        S_, S_, S_, 2, 1);

    // 16) GEMM4: out = att @ wo  [2048 x 2048], K=2048
    gemm_mma<<<dim3(HID_ / 128, S_ / 128, 1), 256, SMEM_GEMM>>>(
        atbh, atbl, 0, woTh, woTl, 0, out, nullptr, nullptr, 0, HID_,
        HID_, HID_, HID_, 0, 0);
}